// round 4
// baseline (speedup 1.0000x reference)
#include <cuda_runtime.h>
#include <math.h>

#define NNODES 100000
#define NEDGES 1200000
#define DIM 64

// ---------------- scratch (device globals; float4 => 16B aligned) ----------
__device__ float4 g_agg4 [NNODES * DIM / 4];  // sum of x[src] per dst
__device__ float4 g_aggw4[NNODES * DIM / 4];  // sum of dinv[src]*x[src] per dst
__device__ float  g_sw   [NNODES];            // sum of dinv[src] per dst
__device__ float  g_dinv [NNODES];            // rsqrt(deg+1)
__device__ int    g_deg  [NNODES];            // in-degree (dst only)

// ---------------- helpers ----------------
__device__ __forceinline__ void red_add_v4(float4* addr, float4 v) {
    asm volatile("red.global.add.v4.f32 [%0], {%1, %2, %3, %4};"
                 :: "l"(addr), "f"(v.x), "f"(v.y), "f"(v.z), "f"(v.w)
                 : "memory");
}

__device__ __forceinline__ void fma4(float4& a, float s, const float4& w) {
    a.x = fmaf(s, w.x, a.x);
    a.y = fmaf(s, w.y, a.y);
    a.z = fmaf(s, w.z, a.z);
    a.w = fmaf(s, w.w, a.w);
}

__device__ __forceinline__ float eluf(float z) {
    return z > 0.0f ? z : expm1f(z);
}

// ---------------- kernels ----------------
__global__ void k_zero() {
    int i = blockIdx.x * blockDim.x + threadIdx.x;
    const int n4 = NNODES * DIM / 4;  // 1.6M float4
    float4 z = make_float4(0.f, 0.f, 0.f, 0.f);
    if (i < n4) {
        g_agg4[i]  = z;
        g_aggw4[i] = z;
    }
    if (i < NNODES / 4) {
        reinterpret_cast<float4*>(g_sw)[i] = z;
        reinterpret_cast<int4*>(g_deg)[i]  = make_int4(0, 0, 0, 0);
    }
}

__global__ void k_deg(const int* __restrict__ dst) {
    int e = blockIdx.x * blockDim.x + threadIdx.x;
    if (e < NEDGES) {
        unsigned d = (unsigned)dst[e];
        if (d < NNODES) atomicAdd(&g_deg[d], 1);
    }
}

__global__ void k_dinv() {
    int i = blockIdx.x * blockDim.x + threadIdx.x;
    if (i < NNODES) g_dinv[i] = rsqrtf((float)g_deg[i] + 1.0f);
}

// 16 threads per edge, each handles one float4 (4 of 64 dims).
// Uniform control flow within the edge's thread group: guards clamp rather
// than early-return, atomics are predicated by zero values instead of
// divergent exits.
__global__ void k_edge(const int* __restrict__ src,
                       const int* __restrict__ dst,
                       const float* __restrict__ x) {
    int idx = blockIdx.x * blockDim.x + threadIdx.x;
    int e = idx >> 4;
    if (e >= NEDGES) return;                   // whole 16-thread group exits together
    int q = idx & 15;
    unsigned s = (unsigned)__ldg(src + e);
    unsigned d = (unsigned)__ldg(dst + e);
    bool ok = (s < NNODES) && (d < NNODES);
    s = ok ? s : 0u;                           // clamp: keep loads/reds in-bounds
    d = ok ? d : 0u;
    float ds = g_dinv[s];
    float4 xv = __ldg(reinterpret_cast<const float4*>(x) + s * 16 + q);
    if (!ok) xv = make_float4(0.f, 0.f, 0.f, 0.f);   // contribute zero, stay uniform
    red_add_v4(&g_agg4[d * 16 + q], xv);
    float4 xw = make_float4(xv.x * ds, xv.y * ds, xv.z * ds, xv.w * ds);
    red_add_v4(&g_aggw4[d * 16 + q], xw);
    if (q == 0) atomicAdd(&g_sw[d], ok ? ds : 0.0f);
}

// Fused node pass: build 4 input vectors per node, 4 matvecs (64x64),
// ELU + weighted combine. 512 threads, 128 nodes/block.
// SMEM: Ws [4][64][64] = 16384 floats; inT [4][64][132] = 33792 floats;
//       nsum [128] floats.  Total 50304 floats = 201216 B (dynamic).
#define INPAD 132
__global__ void __launch_bounds__(512, 1)
k_node(const float* __restrict__ x,
       const float* __restrict__ weights,
       const float* __restrict__ Wg,  const float* __restrict__ bg,
       const float* __restrict__ Wsl, const float* __restrict__ Wn,
       const float* __restrict__ bs,
       const float* __restrict__ Wi,  const float* __restrict__ bi,
       float* __restrict__ out) {
    extern __shared__ float sm[];
    float* Ws   = sm;                 // 16384
    float* inT  = sm + 16384;         // 33792
    float* nsum = inT + 33792;        // 128

    int tid = threadIdx.x;
    int nodeBase = blockIdx.x * 128;

    // ---- stage weights (row-major [k][j], 1024 float4 each) ----
    {
        float4* d4 = reinterpret_cast<float4*>(Ws);
        const float4* s0 = reinterpret_cast<const float4*>(Wg);
        const float4* s1 = reinterpret_cast<const float4*>(Wsl);
        const float4* s2 = reinterpret_cast<const float4*>(Wn);
        const float4* s3 = reinterpret_cast<const float4*>(Wi);
        for (int i = tid; i < 1024; i += 512) {
            d4[i]        = s0[i];
            d4[1024 + i] = s1[i];
            d4[2048 + i] = s2[i];
            d4[3072 + i] = s3[i];
        }
    }

    // ---- stage inputs, transposed [type][k][node] ----
    {
        int node = tid & 127;
        int kq   = tid >> 7;          // 0..3
        int gn   = nodeBase + node;
        bool valid = gn < NNODES;
        int gns = valid ? gn : 0;     // clamped index for loads
        float di  = g_dinv[gns];
        float dsq = di * di;
        float invdeg = 1.0f / fmaxf((float)g_deg[gns], 1.0f);
        if (kq == 0) nsum[node] = valid ? (di * g_sw[gns] + dsq) : 0.0f;

        const float4* x4 = reinterpret_cast<const float4*>(x);
        float4 z = make_float4(0.f, 0.f, 0.f, 0.f);
        for (int k4 = kq; k4 < 16; k4 += 4) {
            float4 xv = valid ? x4[gns * 16 + k4] : z;
            float4 ag = valid ? g_agg4 [gns * 16 + k4] : z;
            float4 aw = valid ? g_aggw4[gns * 16 + k4] : z;
            float4 gc = make_float4(di * aw.x + dsq * xv.x,
                                    di * aw.y + dsq * xv.y,
                                    di * aw.z + dsq * xv.z,
                                    di * aw.w + dsq * xv.w);
            float4 mn = make_float4(invdeg * ag.x, invdeg * ag.y,
                                    invdeg * ag.z, invdeg * ag.w);
            float4 gi = make_float4(xv.x + ag.x, xv.y + ag.y,
                                    xv.z + ag.z, xv.w + ag.w);
            int kb = k4 * 4;
#define ST(t, kk, v) inT[((t) * 64 + (kk)) * INPAD + node] = (v)
            ST(0, kb + 0, gc.x); ST(0, kb + 1, gc.y); ST(0, kb + 2, gc.z); ST(0, kb + 3, gc.w);
            ST(1, kb + 0, xv.x); ST(1, kb + 1, xv.y); ST(1, kb + 2, xv.z); ST(1, kb + 3, xv.w);
            ST(2, kb + 0, mn.x); ST(2, kb + 1, mn.y); ST(2, kb + 2, mn.z); ST(2, kb + 3, mn.w);
            ST(3, kb + 0, gi.x); ST(3, kb + 1, gi.y); ST(3, kb + 2, gi.z); ST(3, kb + 3, gi.w);
#undef ST
        }
    }
    __syncthreads();

    // ---- main matvec loop ----
    int ng = tid & 31;   // node group: nodes ng*4 .. ng*4+3
    int jg = tid >> 5;   // output group: cols jg*4 .. jg*4+3 (warp-uniform)

    float4 accG[4], accS[4], accI[4];
#pragma unroll
    for (int i = 0; i < 4; i++) {
        accG[i] = make_float4(0.f, 0.f, 0.f, 0.f);
        accS[i] = make_float4(0.f, 0.f, 0.f, 0.f);
        accI[i] = make_float4(0.f, 0.f, 0.f, 0.f);
    }

#pragma unroll 4
    for (int k = 0; k < 64; k++) {
        float4 wg  = *reinterpret_cast<const float4*>(&Ws[k * 64 + jg * 4]);
        float4 wsl = *reinterpret_cast<const float4*>(&Ws[4096 + k * 64 + jg * 4]);
        float4 wn  = *reinterpret_cast<const float4*>(&Ws[8192 + k * 64 + jg * 4]);
        float4 wi  = *reinterpret_cast<const float4*>(&Ws[12288 + k * 64 + jg * 4]);

        float4 i0 = *reinterpret_cast<const float4*>(&inT[(0 * 64 + k) * INPAD + ng * 4]);
        float4 i1 = *reinterpret_cast<const float4*>(&inT[(1 * 64 + k) * INPAD + ng * 4]);
        float4 i2 = *reinterpret_cast<const float4*>(&inT[(2 * 64 + k) * INPAD + ng * 4]);
        float4 i3 = *reinterpret_cast<const float4*>(&inT[(3 * 64 + k) * INPAD + ng * 4]);

        fma4(accG[0], i0.x, wg); fma4(accG[1], i0.y, wg);
        fma4(accG[2], i0.z, wg); fma4(accG[3], i0.w, wg);

        fma4(accS[0], i1.x, wsl); fma4(accS[1], i1.y, wsl);
        fma4(accS[2], i1.z, wsl); fma4(accS[3], i1.w, wsl);

        fma4(accS[0], i2.x, wn); fma4(accS[1], i2.y, wn);
        fma4(accS[2], i2.z, wn); fma4(accS[3], i2.w, wn);

        fma4(accI[0], i3.x, wi); fma4(accI[1], i3.y, wi);
        fma4(accI[2], i3.z, wi); fma4(accI[3], i3.w, wi);
    }

    // ---- epilogue: biases, ELU, weighted combine ----
    float w0 = __ldg(weights + 0);
    float w1 = __ldg(weights + 1);
    float w2 = __ldg(weights + 2);
    float4 bgv = __ldg(reinterpret_cast<const float4*>(bg) + jg);
    float4 bsv = __ldg(reinterpret_cast<const float4*>(bs) + jg);
    float4 biv = __ldg(reinterpret_cast<const float4*>(bi) + jg);

#pragma unroll
    for (int i = 0; i < 4; i++) {
        int nloc = ng * 4 + i;
        int gn = nodeBase + nloc;
        if (gn >= NNODES) continue;
        float ns = nsum[nloc];
        float4 vg = make_float4(accG[i].x + bgv.x * ns, accG[i].y + bgv.y * ns,
                                accG[i].z + bgv.z * ns, accG[i].w + bgv.w * ns);
        float4 vs = make_float4(accS[i].x + bsv.x, accS[i].y + bsv.y,
                                accS[i].z + bsv.z, accS[i].w + bsv.w);
        float4 vi = make_float4(accI[i].x + biv.x, accI[i].y + biv.y,
                                accI[i].z + biv.z, accI[i].w + biv.w);
        float4 o;
        o.x = w0 * eluf(vg.x) + w1 * eluf(vs.x) + w2 * eluf(vi.x);
        o.y = w0 * eluf(vg.y) + w1 * eluf(vs.y) + w2 * eluf(vi.y);
        o.z = w0 * eluf(vg.z) + w1 * eluf(vs.z) + w2 * eluf(vi.z);
        o.w = w0 * eluf(vg.w) + w1 * eluf(vs.w) + w2 * eluf(vi.w);
        *reinterpret_cast<float4*>(&out[gn * 64 + jg * 4]) = o;
    }
}

// ---------------- launch ----------------
extern "C" void kernel_launch(void* const* d_in, const int* in_sizes, int n_in,
                              void* d_out, int out_size) {
    const float* x       = (const float*)d_in[0];
    // d_in[1] = x0 (unused by reference ops)
    const float* weights = (const float*)d_in[2];
    const int*   ei      = (const int*)d_in[3];   // int32 (JAX x64 disabled)
    const float* Wg      = (const float*)d_in[4];
    const float* bg      = (const float*)d_in[5];
    const float* Wsl     = (const float*)d_in[6];
    const float* Wn      = (const float*)d_in[7];
    const float* bs      = (const float*)d_in[8];
    const float* Wi      = (const float*)d_in[9];
    const float* bi      = (const float*)d_in[10];

    const int* src = ei;
    const int* dst = ei + NEDGES;

    {
        int n4 = NNODES * DIM / 4;  // 1.6M
        k_zero<<<(n4 + 255) / 256, 256>>>();
    }
    k_deg<<<(NEDGES + 255) / 256, 256>>>(dst);
    k_dinv<<<(NNODES + 255) / 256, 256>>>();
    {
        long long total = (long long)NEDGES * 16;
        k_edge<<<(int)((total + 255) / 256), 256>>>(src, dst, x);
    }
    {
        const int smem = 201216;
        (void)cudaFuncSetAttribute(k_node, cudaFuncAttributeMaxDynamicSharedMemorySize, smem);
        int blocks = (NNODES + 127) / 128;  // 782
        k_node<<<blocks, 512, smem>>>(x, weights, Wg, bg, Wsl, Wn, bs, Wi, bi,
                                      (float*)d_out);
    }
}

// round 5
// speedup vs baseline: 1.1605x; 1.1605x over previous
#include <cuda_runtime.h>
#include <math.h>

#define NNODES 100000
#define NEDGES 1200000
#define DIM 64
#define NCHUNK ((NNODES + 1023) / 1024)   // 98

typedef unsigned long long ull;

// ---------------- scratch (device globals) ----------------
__device__ float4 g_agg4 [NNODES * DIM / 4];  // sum of x[src] per dst
__device__ float4 g_aggw4[NNODES * DIM / 4];  // sum of dinv[src]*x[src] per dst
__device__ float  g_sw   [NNODES];            // sum of dinv[src] per dst
__device__ float  g_dinv [NNODES];            // rsqrt(deg+1)
__device__ int    g_deg  [NNODES];            // in-degree (dst only)
__device__ int    g_start[NNODES];            // CSR row start (exclusive scan of deg)
__device__ int    g_cursor[NNODES];           // placement cursors
__device__ int    g_bsum [NCHUNK];            // per-chunk sums
__device__ int    g_boff [NCHUNK];            // scanned chunk offsets
__device__ int    g_csr  [NEDGES];            // src ids grouped by dst

// ---------------- helpers ----------------
__device__ __forceinline__ ull fma2(ull a, ull b, ull c) {
    ull d;
    asm("fma.rn.f32x2 %0, %1, %2, %3;" : "=l"(d) : "l"(a), "l"(b), "l"(c));
    return d;
}
__device__ __forceinline__ ull dup2(float s) {
    ull d; unsigned u = __float_as_uint(s);
    asm("mov.b64 %0, {%1, %1};" : "=l"(d) : "r"(u));
    return d;
}
__device__ __forceinline__ float2 unpack2(ull v) {
    unsigned lo, hi;
    asm("mov.b64 {%0, %1}, %2;" : "=r"(lo), "=r"(hi) : "l"(v));
    return make_float2(__uint_as_float(lo), __uint_as_float(hi));
}
__device__ __forceinline__ float eluf(float z) {
    return z > 0.0f ? z : expm1f(z);
}

// ---------------- CSR build ----------------
__global__ void k_zero_deg() {
    int i = blockIdx.x * blockDim.x + threadIdx.x;
    if (i < NNODES) g_deg[i] = 0;
}

__global__ void k_deg(const int* __restrict__ dst) {
    int e = blockIdx.x * blockDim.x + threadIdx.x;
    if (e < NEDGES) {
        unsigned d = (unsigned)dst[e];
        if (d < NNODES) atomicAdd(&g_deg[d], 1);
    }
}

// per-chunk (1024 elems) exclusive scan; chunk totals to g_bsum
__global__ void k_scan1() {
    __shared__ int s[256];
    int blk = blockIdx.x, tid = threadIdx.x;
    int base = blk * 1024 + tid * 4;
    int d0 = 0, d1 = 0, d2 = 0, d3 = 0;
    if (base + 0 < NNODES) d0 = g_deg[base + 0];
    if (base + 1 < NNODES) d1 = g_deg[base + 1];
    if (base + 2 < NNODES) d2 = g_deg[base + 2];
    if (base + 3 < NNODES) d3 = g_deg[base + 3];
    int sum = d0 + d1 + d2 + d3;
    s[tid] = sum;
    __syncthreads();
    for (int off = 1; off < 256; off <<= 1) {
        int add = (tid >= off) ? s[tid - off] : 0;
        __syncthreads();
        s[tid] += add;
        __syncthreads();
    }
    int incl = s[tid];
    int run = incl - sum;  // exclusive
    if (tid == 255) g_bsum[blk] = incl;
    if (base + 0 < NNODES) { g_start[base + 0] = run; run += d0; }
    if (base + 1 < NNODES) { g_start[base + 1] = run; run += d1; }
    if (base + 2 < NNODES) { g_start[base + 2] = run; run += d2; }
    if (base + 3 < NNODES) { g_start[base + 3] = run; }
}

__global__ void k_scan2() {
    __shared__ int s[128];
    int tid = threadIdx.x;
    int v = (tid < NCHUNK) ? g_bsum[tid] : 0;
    s[tid] = v;
    __syncthreads();
    for (int off = 1; off < 128; off <<= 1) {
        int add = (tid >= off) ? s[tid - off] : 0;
        __syncthreads();
        s[tid] += add;
        __syncthreads();
    }
    if (tid < NCHUNK) g_boff[tid] = s[tid] - v;  // exclusive
}

// finalize offsets, init cursors, compute dinv
__global__ void k_scan3() {
    int i = blockIdx.x * blockDim.x + threadIdx.x;
    if (i < NNODES) {
        int v = g_start[i] + g_boff[i >> 10];
        g_start[i]  = v;
        g_cursor[i] = v;
        g_dinv[i]   = rsqrtf((float)g_deg[i] + 1.0f);
    }
}

__global__ void k_place(const int* __restrict__ src,
                        const int* __restrict__ dst) {
    int e = blockIdx.x * blockDim.x + threadIdx.x;
    if (e >= NEDGES) return;
    unsigned s = (unsigned)src[e];
    unsigned d = (unsigned)dst[e];
    if (s >= NNODES || d >= NNODES) return;
    int pos = atomicAdd(&g_cursor[d], 1);
    if (pos < NEDGES) g_csr[pos] = (int)s;
}

// ---------------- gather (no atomics) ----------------
// 4 threads per node; each handles 4 float4 (16 dims).
__global__ void k_gather(const float* __restrict__ x) {
    int idx = blockIdx.x * blockDim.x + threadIdx.x;
    int node = idx >> 2;
    if (node >= NNODES) return;
    int part = idx & 3;

    int beg = g_start[node];
    int end = beg + g_deg[node];

    float4 acc[4], accw[4];
#pragma unroll
    for (int j = 0; j < 4; j++) {
        acc[j]  = make_float4(0.f, 0.f, 0.f, 0.f);
        accw[j] = make_float4(0.f, 0.f, 0.f, 0.f);
    }
    float swacc = 0.0f;

    const float4* x4 = reinterpret_cast<const float4*>(x);
    for (int i = beg; i < end; i++) {
        int s = __ldg(g_csr + i);
        float ds = __ldg(g_dinv + s);
        swacc += ds;
        const float4* xs = x4 + s * 16 + part * 4;
#pragma unroll
        for (int j = 0; j < 4; j++) {
            float4 xv = __ldg(xs + j);
            acc[j].x += xv.x; acc[j].y += xv.y; acc[j].z += xv.z; acc[j].w += xv.w;
            accw[j].x = fmaf(ds, xv.x, accw[j].x);
            accw[j].y = fmaf(ds, xv.y, accw[j].y);
            accw[j].z = fmaf(ds, xv.z, accw[j].z);
            accw[j].w = fmaf(ds, xv.w, accw[j].w);
        }
    }
    int base = node * 16 + part * 4;
#pragma unroll
    for (int j = 0; j < 4; j++) {
        g_agg4 [base + j] = acc[j];
        g_aggw4[base + j] = accw[j];
    }
    if (part == 0) g_sw[node] = swacc;
}

// ---------------- fused node pass (f32x2 FMA) ----------------
// SMEM: Ws [4][64][64] = 16384 floats; inT [4][64][132] = 33792 floats;
//       nsum [128] floats.  Total 201216 B dynamic.
#define INPAD 132
__global__ void __launch_bounds__(512, 1)
k_node(const float* __restrict__ x,
       const float* __restrict__ weights,
       const float* __restrict__ Wg,  const float* __restrict__ bg,
       const float* __restrict__ Wsl, const float* __restrict__ Wn,
       const float* __restrict__ bs,
       const float* __restrict__ Wi,  const float* __restrict__ bi,
       float* __restrict__ out) {
    extern __shared__ float sm[];
    float* Ws   = sm;                 // 16384
    float* inT  = sm + 16384;         // 33792
    float* nsum = inT + 33792;        // 128

    int tid = threadIdx.x;
    int nodeBase = blockIdx.x * 128;

    // ---- stage weights ----
    {
        float4* d4 = reinterpret_cast<float4*>(Ws);
        const float4* s0 = reinterpret_cast<const float4*>(Wg);
        const float4* s1 = reinterpret_cast<const float4*>(Wsl);
        const float4* s2 = reinterpret_cast<const float4*>(Wn);
        const float4* s3 = reinterpret_cast<const float4*>(Wi);
        for (int i = tid; i < 1024; i += 512) {
            d4[i]        = s0[i];
            d4[1024 + i] = s1[i];
            d4[2048 + i] = s2[i];
            d4[3072 + i] = s3[i];
        }
    }

    // ---- stage inputs, transposed [type][k][node] ----
    {
        int node = tid & 127;
        int kq   = tid >> 7;          // 0..3
        int gn   = nodeBase + node;
        bool valid = gn < NNODES;
        int gns = valid ? gn : 0;
        float di  = g_dinv[gns];
        float dsq = di * di;
        float invdeg = 1.0f / fmaxf((float)g_deg[gns], 1.0f);
        if (kq == 0) nsum[node] = valid ? (di * g_sw[gns] + dsq) : 0.0f;

        const float4* x4 = reinterpret_cast<const float4*>(x);
        float4 z = make_float4(0.f, 0.f, 0.f, 0.f);
        for (int k4 = kq; k4 < 16; k4 += 4) {
            float4 xv = valid ? x4[gns * 16 + k4] : z;
            float4 ag = valid ? g_agg4 [gns * 16 + k4] : z;
            float4 aw = valid ? g_aggw4[gns * 16 + k4] : z;
            float4 gc = make_float4(di * aw.x + dsq * xv.x,
                                    di * aw.y + dsq * xv.y,
                                    di * aw.z + dsq * xv.z,
                                    di * aw.w + dsq * xv.w);
            float4 mn = make_float4(invdeg * ag.x, invdeg * ag.y,
                                    invdeg * ag.z, invdeg * ag.w);
            float4 gi = make_float4(xv.x + ag.x, xv.y + ag.y,
                                    xv.z + ag.z, xv.w + ag.w);
            int kb = k4 * 4;
#define ST(t, kk, v) inT[((t) * 64 + (kk)) * INPAD + node] = (v)
            ST(0, kb + 0, gc.x); ST(0, kb + 1, gc.y); ST(0, kb + 2, gc.z); ST(0, kb + 3, gc.w);
            ST(1, kb + 0, xv.x); ST(1, kb + 1, xv.y); ST(1, kb + 2, xv.z); ST(1, kb + 3, xv.w);
            ST(2, kb + 0, mn.x); ST(2, kb + 1, mn.y); ST(2, kb + 2, mn.z); ST(2, kb + 3, mn.w);
            ST(3, kb + 0, gi.x); ST(3, kb + 1, gi.y); ST(3, kb + 2, gi.z); ST(3, kb + 3, gi.w);
#undef ST
        }
    }
    __syncthreads();

    // ---- main matvec loop (packed f32x2) ----
    int ng = tid & 31;   // node group: nodes ng*4 .. ng*4+3
    int jg = tid >> 5;   // output cols jg*4 .. jg*4+3 (warp-uniform)

    // acc[j*2 + p]: p=0 -> nodes {0,1}, p=1 -> nodes {2,3} of this group
    ull accG[8], accS[8], accI[8];
#pragma unroll
    for (int i = 0; i < 8; i++) { accG[i] = 0ull; accS[i] = 0ull; accI[i] = 0ull; }

#define DOMV(ACC, W, IN) {                                              \
    ull w0 = dup2((W).x), w1 = dup2((W).y),                             \
        w2 = dup2((W).z), w3 = dup2((W).w);                             \
    ACC[0] = fma2((IN).x, w0, ACC[0]); ACC[1] = fma2((IN).y, w0, ACC[1]); \
    ACC[2] = fma2((IN).x, w1, ACC[2]); ACC[3] = fma2((IN).y, w1, ACC[3]); \
    ACC[4] = fma2((IN).x, w2, ACC[4]); ACC[5] = fma2((IN).y, w2, ACC[5]); \
    ACC[6] = fma2((IN).x, w3, ACC[6]); ACC[7] = fma2((IN).y, w3, ACC[7]); }

#pragma unroll 4
    for (int k = 0; k < 64; k++) {
        float4 wg  = *reinterpret_cast<const float4*>(&Ws[k * 64 + jg * 4]);
        float4 wsl = *reinterpret_cast<const float4*>(&Ws[4096 + k * 64 + jg * 4]);
        float4 wn  = *reinterpret_cast<const float4*>(&Ws[8192 + k * 64 + jg * 4]);
        float4 wi  = *reinterpret_cast<const float4*>(&Ws[12288 + k * 64 + jg * 4]);

        ulonglong2 i0 = *reinterpret_cast<const ulonglong2*>(&inT[(0 * 64 + k) * INPAD + ng * 4]);
        ulonglong2 i1 = *reinterpret_cast<const ulonglong2*>(&inT[(1 * 64 + k) * INPAD + ng * 4]);
        ulonglong2 i2 = *reinterpret_cast<const ulonglong2*>(&inT[(2 * 64 + k) * INPAD + ng * 4]);
        ulonglong2 i3 = *reinterpret_cast<const ulonglong2*>(&inT[(3 * 64 + k) * INPAD + ng * 4]);

        DOMV(accG, wg,  i0);
        DOMV(accS, wsl, i1);
        DOMV(accS, wn,  i2);
        DOMV(accI, wi,  i3);
    }
#undef DOMV

    // ---- epilogue ----
    float w0 = __ldg(weights + 0);
    float w1 = __ldg(weights + 1);
    float w2 = __ldg(weights + 2);
    float4 bgv = __ldg(reinterpret_cast<const float4*>(bg) + jg);
    float4 bsv = __ldg(reinterpret_cast<const float4*>(bs) + jg);
    float4 biv = __ldg(reinterpret_cast<const float4*>(bi) + jg);
    float bga[4] = {bgv.x, bgv.y, bgv.z, bgv.w};
    float bsa[4] = {bsv.x, bsv.y, bsv.z, bsv.w};
    float bia[4] = {biv.x, biv.y, biv.z, biv.w};

#pragma unroll
    for (int i = 0; i < 4; i++) {       // local node index within group
        int p = i >> 1, h = i & 1;
        int nloc = ng * 4 + i;
        int gn = nodeBase + nloc;
        if (gn >= NNODES) continue;
        float ns = nsum[nloc];
        float o[4];
#pragma unroll
        for (int j = 0; j < 4; j++) {
            float2 fg = unpack2(accG[j * 2 + p]);
            float2 fs = unpack2(accS[j * 2 + p]);
            float2 fi = unpack2(accI[j * 2 + p]);
            float vg = (h ? fg.y : fg.x) + bga[j] * ns;
            float vs = (h ? fs.y : fs.x) + bsa[j];
            float vi = (h ? fi.y : fi.x) + bia[j];
            o[j] = w0 * eluf(vg) + w1 * eluf(vs) + w2 * eluf(vi);
        }
        *reinterpret_cast<float4*>(&out[gn * 64 + jg * 4]) =
            make_float4(o[0], o[1], o[2], o[3]);
    }
}

// ---------------- launch ----------------
extern "C" void kernel_launch(void* const* d_in, const int* in_sizes, int n_in,
                              void* d_out, int out_size) {
    const float* x       = (const float*)d_in[0];
    // d_in[1] = x0 (unused by reference ops)
    const float* weights = (const float*)d_in[2];
    const int*   ei      = (const int*)d_in[3];   // int32
    const float* Wg      = (const float*)d_in[4];
    const float* bg      = (const float*)d_in[5];
    const float* Wsl     = (const float*)d_in[6];
    const float* Wn      = (const float*)d_in[7];
    const float* bs      = (const float*)d_in[8];
    const float* Wi      = (const float*)d_in[9];
    const float* bi      = (const float*)d_in[10];

    const int* src = ei;
    const int* dst = ei + NEDGES;

    k_zero_deg<<<(NNODES + 255) / 256, 256>>>();
    k_deg<<<(NEDGES + 255) / 256, 256>>>(dst);
    k_scan1<<<NCHUNK, 256>>>();
    k_scan2<<<1, 128>>>();
    k_scan3<<<(NNODES + 255) / 256, 256>>>();
    k_place<<<(NEDGES + 255) / 256, 256>>>(src, dst);
    k_gather<<<(NNODES * 4 + 255) / 256, 256>>>(x);
    {
        const int smem = 201216;
        (void)cudaFuncSetAttribute(k_node, cudaFuncAttributeMaxDynamicSharedMemorySize, smem);
        int blocks = (NNODES + 127) / 128;  // 782
        k_node<<<blocks, 512, smem>>>(x, weights, Wg, bg, Wsl, Wn, bs, Wi, bi,
                                      (float*)d_out);
    }
}

// round 7
// speedup vs baseline: 1.2881x; 1.1099x over previous
// R7 = R6 resubmission (container infra-flake on R6; kernel unchanged).
#include <cuda_runtime.h>
#include <math.h>

#define NNODES 100000
#define NEDGES 1200000
#define DIM 64
#define NCHUNK ((NNODES + 1023) / 1024)   // 98

typedef unsigned long long ull;

// ---------------- scratch (device globals) ----------------
__device__ float g_dinv [NNODES];            // rsqrt(deg+1)
__device__ int   g_deg  [NNODES];            // in-degree (dst only)
__device__ int   g_start[NNODES];            // CSR row start
__device__ int   g_cursor[NNODES];           // placement cursors
__device__ int   g_bsum [NCHUNK];
__device__ int   g_boff [NCHUNK];
__device__ int   g_csr  [NEDGES];            // src ids grouped by dst

// ---------------- helpers ----------------
__device__ __forceinline__ ull fma2(ull a, ull b, ull c) {
    ull d;
    asm("fma.rn.f32x2 %0, %1, %2, %3;" : "=l"(d) : "l"(a), "l"(b), "l"(c));
    return d;
}
__device__ __forceinline__ ull dup2(float s) {
    ull d; unsigned u = __float_as_uint(s);
    asm("mov.b64 %0, {%1, %1};" : "=l"(d) : "r"(u));
    return d;
}
__device__ __forceinline__ float2 unpack2(ull v) {
    unsigned lo, hi;
    asm("mov.b64 {%0, %1}, %2;" : "=r"(lo), "=r"(hi) : "l"(v));
    return make_float2(__uint_as_float(lo), __uint_as_float(hi));
}
__device__ __forceinline__ float eluf(float z) {
    return z > 0.0f ? z : expm1f(z);
}

// ---------------- CSR build ----------------
__global__ void k_zero_deg() {
    int i = blockIdx.x * blockDim.x + threadIdx.x;
    if (i < NNODES) g_deg[i] = 0;
}

__global__ void k_deg(const int* __restrict__ dst) {
    int e = blockIdx.x * blockDim.x + threadIdx.x;
    if (e < NEDGES) {
        unsigned d = (unsigned)dst[e];
        if (d < NNODES) atomicAdd(&g_deg[d], 1);
    }
}

__global__ void k_scan1() {
    __shared__ int s[256];
    int blk = blockIdx.x, tid = threadIdx.x;
    int base = blk * 1024 + tid * 4;
    int d0 = 0, d1 = 0, d2 = 0, d3 = 0;
    if (base + 0 < NNODES) d0 = g_deg[base + 0];
    if (base + 1 < NNODES) d1 = g_deg[base + 1];
    if (base + 2 < NNODES) d2 = g_deg[base + 2];
    if (base + 3 < NNODES) d3 = g_deg[base + 3];
    int sum = d0 + d1 + d2 + d3;
    s[tid] = sum;
    __syncthreads();
    for (int off = 1; off < 256; off <<= 1) {
        int add = (tid >= off) ? s[tid - off] : 0;
        __syncthreads();
        s[tid] += add;
        __syncthreads();
    }
    int incl = s[tid];
    int run = incl - sum;
    if (tid == 255) g_bsum[blk] = incl;
    if (base + 0 < NNODES) { g_start[base + 0] = run; run += d0; }
    if (base + 1 < NNODES) { g_start[base + 1] = run; run += d1; }
    if (base + 2 < NNODES) { g_start[base + 2] = run; run += d2; }
    if (base + 3 < NNODES) { g_start[base + 3] = run; }
}

__global__ void k_scan2() {
    __shared__ int s[128];
    int tid = threadIdx.x;
    int v = (tid < NCHUNK) ? g_bsum[tid] : 0;
    s[tid] = v;
    __syncthreads();
    for (int off = 1; off < 128; off <<= 1) {
        int add = (tid >= off) ? s[tid - off] : 0;
        __syncthreads();
        s[tid] += add;
        __syncthreads();
    }
    if (tid < NCHUNK) g_boff[tid] = s[tid] - v;
}

__global__ void k_scan3() {
    int i = blockIdx.x * blockDim.x + threadIdx.x;
    if (i < NNODES) {
        int v = g_start[i] + g_boff[i >> 10];
        g_start[i]  = v;
        g_cursor[i] = v;
        g_dinv[i]   = rsqrtf((float)g_deg[i] + 1.0f);
    }
}

__global__ void k_place(const int* __restrict__ src,
                        const int* __restrict__ dst) {
    int e = blockIdx.x * blockDim.x + threadIdx.x;
    if (e >= NEDGES) return;
    unsigned s = (unsigned)src[e];
    unsigned d = (unsigned)dst[e];
    if (s >= NNODES || d >= NNODES) return;
    int pos = atomicAdd(&g_cursor[d], 1);
    if (pos < NEDGES) g_csr[pos] = (int)s;
}

// ---------------- fused gather + matvec ----------------
// 512 threads, 128 nodes/block. Phase B: quads (4 threads) gather neighbor
// sums in registers, transform, store transposed tiles in smem. Phase C:
// packed f32x2 matvec + ELU + combine.
// SMEM: Ws 16384 + inT 33792 + nsum 128 = 50304 floats = 201216 B.
#define INPAD 132
__global__ void __launch_bounds__(512, 1)
k_fused(const float* __restrict__ x,
        const float* __restrict__ weights,
        const float* __restrict__ Wg,  const float* __restrict__ bg,
        const float* __restrict__ Wsl, const float* __restrict__ Wn,
        const float* __restrict__ bs,
        const float* __restrict__ Wi,  const float* __restrict__ bi,
        float* __restrict__ out) {
    extern __shared__ float sm[];
    float* Ws   = sm;                 // 16384
    float* inT  = sm + 16384;         // 33792
    float* nsum = inT + 33792;        // 128

    int tid = threadIdx.x;
    int nodeBase = blockIdx.x * 128;

    // ---- phase A: stage weights ----
    {
        float4* d4 = reinterpret_cast<float4*>(Ws);
        const float4* s0 = reinterpret_cast<const float4*>(Wg);
        const float4* s1 = reinterpret_cast<const float4*>(Wsl);
        const float4* s2 = reinterpret_cast<const float4*>(Wn);
        const float4* s3 = reinterpret_cast<const float4*>(Wi);
        for (int i = tid; i < 1024; i += 512) {
            d4[i]        = s0[i];
            d4[1024 + i] = s1[i];
            d4[2048 + i] = s2[i];
            d4[3072 + i] = s3[i];
        }
    }

    // ---- phase B: gather per quad, transform, write inT ----
    {
        int node = tid >> 2;          // 0..127
        int part = tid & 3;           // 16 dims each
        int lane = tid & 31;
        unsigned qmask = 0xFu << (lane & ~3);
        int gn = nodeBase + node;
        bool valid = gn < NNODES;
        int gns = valid ? gn : 0;

        int beg = g_start[gns];
        int deg = valid ? g_deg[gns] : 0;
        int end = beg + deg;

        float4 acc[4], accw[4];
#pragma unroll
        for (int j = 0; j < 4; j++) {
            acc[j]  = make_float4(0.f, 0.f, 0.f, 0.f);
            accw[j] = make_float4(0.f, 0.f, 0.f, 0.f);
        }
        float swacc = 0.0f;

        const float4* x4 = reinterpret_cast<const float4*>(x);
        for (int i = beg; i < end; i++) {
            int sraw = 0; float draw = 0.f;
            if (part == 0) {
                sraw = __ldg(g_csr + i);
                draw = __ldg(g_dinv + sraw);
            }
            int s    = __shfl_sync(qmask, sraw, lane & ~3);
            float ds = __shfl_sync(qmask, draw, lane & ~3);
            swacc += ds;
            const float4* xs = x4 + s * 16 + part * 4;
#pragma unroll
            for (int j = 0; j < 4; j++) {
                float4 xv = __ldg(xs + j);
                acc[j].x += xv.x; acc[j].y += xv.y;
                acc[j].z += xv.z; acc[j].w += xv.w;
                accw[j].x = fmaf(ds, xv.x, accw[j].x);
                accw[j].y = fmaf(ds, xv.y, accw[j].y);
                accw[j].z = fmaf(ds, xv.z, accw[j].z);
                accw[j].w = fmaf(ds, xv.w, accw[j].w);
            }
        }

        float di  = g_dinv[gns];
        float dsq = di * di;
        float invdeg = 1.0f / fmaxf((float)deg, 1.0f);
        if (part == 0) nsum[node] = valid ? (di * swacc + dsq) : 0.0f;

        float4 z = make_float4(0.f, 0.f, 0.f, 0.f);
#pragma unroll
        for (int j = 0; j < 4; j++) {
            float4 xv = valid ? __ldg(x4 + gns * 16 + part * 4 + j) : z;
            float4 ag = valid ? acc[j]  : z;
            float4 aw = valid ? accw[j] : z;
            float4 gc = make_float4(di * aw.x + dsq * xv.x,
                                    di * aw.y + dsq * xv.y,
                                    di * aw.z + dsq * xv.z,
                                    di * aw.w + dsq * xv.w);
            float4 mn = make_float4(invdeg * ag.x, invdeg * ag.y,
                                    invdeg * ag.z, invdeg * ag.w);
            float4 gi = make_float4(xv.x + ag.x, xv.y + ag.y,
                                    xv.z + ag.z, xv.w + ag.w);
            int kb = part * 16 + j * 4;
#define ST(t, kk, v) inT[((t) * 64 + (kk)) * INPAD + node] = (v)
            ST(0, kb + 0, gc.x); ST(0, kb + 1, gc.y); ST(0, kb + 2, gc.z); ST(0, kb + 3, gc.w);
            ST(1, kb + 0, xv.x); ST(1, kb + 1, xv.y); ST(1, kb + 2, xv.z); ST(1, kb + 3, xv.w);
            ST(2, kb + 0, mn.x); ST(2, kb + 1, mn.y); ST(2, kb + 2, mn.z); ST(2, kb + 3, mn.w);
            ST(3, kb + 0, gi.x); ST(3, kb + 1, gi.y); ST(3, kb + 2, gi.z); ST(3, kb + 3, gi.w);
#undef ST
        }
    }
    __syncthreads();

    // ---- phase C: packed f32x2 matvec ----
    int ng = tid & 31;   // node group: nodes ng*4 .. ng*4+3
    int jg = tid >> 5;   // output cols jg*4 .. jg*4+3 (warp-uniform)

    ull accG[8], accS[8], accI[8];
#pragma unroll
    for (int i = 0; i < 8; i++) { accG[i] = 0ull; accS[i] = 0ull; accI[i] = 0ull; }

#define DOMV(ACC, W, IN) {                                              \
    ull w0 = dup2((W).x), w1 = dup2((W).y),                             \
        w2 = dup2((W).z), w3 = dup2((W).w);                             \
    ACC[0] = fma2((IN).x, w0, ACC[0]); ACC[1] = fma2((IN).y, w0, ACC[1]); \
    ACC[2] = fma2((IN).x, w1, ACC[2]); ACC[3] = fma2((IN).y, w1, ACC[3]); \
    ACC[4] = fma2((IN).x, w2, ACC[4]); ACC[5] = fma2((IN).y, w2, ACC[5]); \
    ACC[6] = fma2((IN).x, w3, ACC[6]); ACC[7] = fma2((IN).y, w3, ACC[7]); }

#pragma unroll 4
    for (int k = 0; k < 64; k++) {
        float4 wg  = *reinterpret_cast<const float4*>(&Ws[k * 64 + jg * 4]);
        float4 wsl = *reinterpret_cast<const float4*>(&Ws[4096 + k * 64 + jg * 4]);
        float4 wn  = *reinterpret_cast<const float4*>(&Ws[8192 + k * 64 + jg * 4]);
        float4 wi  = *reinterpret_cast<const float4*>(&Ws[12288 + k * 64 + jg * 4]);

        ulonglong2 i0 = *reinterpret_cast<const ulonglong2*>(&inT[(0 * 64 + k) * INPAD + ng * 4]);
        ulonglong2 i1 = *reinterpret_cast<const ulonglong2*>(&inT[(1 * 64 + k) * INPAD + ng * 4]);
        ulonglong2 i2 = *reinterpret_cast<const ulonglong2*>(&inT[(2 * 64 + k) * INPAD + ng * 4]);
        ulonglong2 i3 = *reinterpret_cast<const ulonglong2*>(&inT[(3 * 64 + k) * INPAD + ng * 4]);

        DOMV(accG, wg,  i0);
        DOMV(accS, wsl, i1);
        DOMV(accS, wn,  i2);
        DOMV(accI, wi,  i3);
    }
#undef DOMV

    // ---- epilogue ----
    float w0 = __ldg(weights + 0);
    float w1 = __ldg(weights + 1);
    float w2 = __ldg(weights + 2);
    float4 bgv = __ldg(reinterpret_cast<const float4*>(bg) + jg);
    float4 bsv = __ldg(reinterpret_cast<const float4*>(bs) + jg);
    float4 biv = __ldg(reinterpret_cast<const float4*>(bi) + jg);
    float bga[4] = {bgv.x, bgv.y, bgv.z, bgv.w};
    float bsa[4] = {bsv.x, bsv.y, bsv.z, bsv.w};
    float bia[4] = {biv.x, biv.y, biv.z, biv.w};

#pragma unroll
    for (int i = 0; i < 4; i++) {
        int p = i >> 1, h = i & 1;
        int nloc = ng * 4 + i;
        int gn = nodeBase + nloc;
        if (gn >= NNODES) continue;
        float ns = nsum[nloc];
        float o[4];
#pragma unroll
        for (int j = 0; j < 4; j++) {
            float2 fg = unpack2(accG[j * 2 + p]);
            float2 fs = unpack2(accS[j * 2 + p]);
            float2 fi = unpack2(accI[j * 2 + p]);
            float vg = (h ? fg.y : fg.x) + bga[j] * ns;
            float vs = (h ? fs.y : fs.x) + bsa[j];
            float vi = (h ? fi.y : fi.x) + bia[j];
            o[j] = w0 * eluf(vg) + w1 * eluf(vs) + w2 * eluf(vi);
        }
        *reinterpret_cast<float4*>(&out[gn * 64 + jg * 4]) =
            make_float4(o[0], o[1], o[2], o[3]);
    }
}

// ---------------- launch ----------------
extern "C" void kernel_launch(void* const* d_in, const int* in_sizes, int n_in,
                              void* d_out, int out_size) {
    const float* x       = (const float*)d_in[0];
    // d_in[1] = x0 (unused by reference ops)
    const float* weights = (const float*)d_in[2];
    const int*   ei      = (const int*)d_in[3];   // int32
    const float* Wg      = (const float*)d_in[4];
    const float* bg      = (const float*)d_in[5];
    const float* Wsl     = (const float*)d_in[6];
    const float* Wn      = (const float*)d_in[7];
    const float* bs      = (const float*)d_in[8];
    const float* Wi      = (const float*)d_in[9];
    const float* bi      = (const float*)d_in[10];

    const int* src = ei;
    const int* dst = ei + NEDGES;

    k_zero_deg<<<(NNODES + 255) / 256, 256>>>();
    k_deg<<<(NEDGES + 255) / 256, 256>>>(dst);
    k_scan1<<<NCHUNK, 256>>>();
    k_scan2<<<1, 128>>>();
    k_scan3<<<(NNODES + 255) / 256, 256>>>();
    k_place<<<(NEDGES + 255) / 256, 256>>>(src, dst);
    {
        const int smem = 201216;
        (void)cudaFuncSetAttribute(k_fused, cudaFuncAttributeMaxDynamicSharedMemorySize, smem);
        int blocks = (NNODES + 127) / 128;  // 782
        k_fused<<<blocks, 512, smem>>>(x, weights, Wg, bg, Wsl, Wn, bs, Wi, bi,
                                       (float*)d_out);
    }
}